// round 6
// baseline (speedup 1.0000x reference)
#include <cuda_runtime.h>
#include <cuda_bf16.h>

#define BATCH 32
#define NN    512
#define MM    512
#define DD    64
#define LDIAG 1023           // N + M - 1 anti-diagonals
#define BIGF  1e30f

// Scratch: FULL distance (x2 + y2 - 2*dot) in diagonal layout:
//   g_Ddiag[b][d][r] = D[b][r][d-r],  d = r + j (0-based), r = row.
// 32 * 1023 * 512 * 4B = ~64 MB (fits in L2). Invalid slots never read by DP.
__device__ float g_Ddiag[(size_t)BATCH * LDIAG * NN];

// ---------------------------------------------------------------------------
// Kernel 1: D for a 128x128 tile, 8x8 register microtile per thread,
// k-major (transposed) smem for conflict-free float4 operand loads,
// norms computed in-block and folded, diagonal-layout coalesced store.
// Dynamic smem union:
//   stage A: Xs[64][128] | Ys[64][128]            (16384 floats)
//   stage B: Dt[128][130]                          (16640 floats)
//   always:  x2s[128], y2s[128] at offset 16640    (256 floats)
// total = 16896 floats = 67584 B
// ---------------------------------------------------------------------------
#define DIST_SMEM_BYTES (16896 * 4)

__global__ __launch_bounds__(256) void dist_kernel(const float* __restrict__ X,
                                                   const float* __restrict__ Y) {
    extern __shared__ float sm[];
    float* Xs  = sm;                 // [64][128] k-major
    float* Ys  = sm + 64 * 128;      // [64][128] k-major
    float* Dt  = sm;                 // [128][130] (reuses Xs/Ys after barrier)
    float* x2s = sm + 16640;
    float* y2s = x2s + 128;

    const int b  = blockIdx.z;
    const int i0 = blockIdx.y * 128;
    const int j0 = blockIdx.x * 128;
    const int tid = threadIdx.x;

    const float* Xg = X + ((size_t)b * NN + i0) * DD;
    const float* Yg = Y + ((size_t)b * MM + j0) * DD;

    // Load + transpose to k-major. Consecutive lanes take consecutive rows so
    // the 4 scalar STS per float4 are conflict-free (stride-1 within warp).
    for (int l = tid; l < 128 * 16; l += 256) {
        int kq = l >> 7;             // 0..15 (float4 chunk along k)
        int r  = l & 127;            // row within tile
        float4 vx = *(const float4*)(Xg + (size_t)r * DD + kq * 4);
        float4 vy = *(const float4*)(Yg + (size_t)r * DD + kq * 4);
        Xs[(kq * 4 + 0) * 128 + r] = vx.x;
        Xs[(kq * 4 + 1) * 128 + r] = vx.y;
        Xs[(kq * 4 + 2) * 128 + r] = vx.z;
        Xs[(kq * 4 + 3) * 128 + r] = vx.w;
        Ys[(kq * 4 + 0) * 128 + r] = vy.x;
        Ys[(kq * 4 + 1) * 128 + r] = vy.y;
        Ys[(kq * 4 + 2) * 128 + r] = vy.z;
        Ys[(kq * 4 + 3) * 128 + r] = vy.w;
    }
    __syncthreads();

    // Row norms from k-major smem (column sums; conflict-free, consecutive lanes)
    if (tid < 128) {
        float s = 0.0f;
        #pragma unroll 8
        for (int k = 0; k < 64; ++k) { float v = Xs[k * 128 + tid]; s += v * v; }
        x2s[tid] = s;
    } else {
        int c = tid - 128;
        float s = 0.0f;
        #pragma unroll 8
        for (int k = 0; k < 64; ++k) { float v = Ys[k * 128 + c]; s += v * v; }
        y2s[c] = s;
    }

    // 8x8 microtile FMA stage
    const int tx = tid & 15, ty = tid >> 4;
    float acc[8][8];
    #pragma unroll
    for (int i = 0; i < 8; i++)
        #pragma unroll
        for (int j = 0; j < 8; j++) acc[i][j] = 0.0f;

    const float* xp = Xs + ty * 8;
    const float* yp = Ys + tx * 8;
    #pragma unroll 4
    for (int k = 0; k < 64; ++k) {
        float4 a0 = *(const float4*)(xp + k * 128);
        float4 a1 = *(const float4*)(xp + k * 128 + 4);
        float4 b0 = *(const float4*)(yp + k * 128);
        float4 b1 = *(const float4*)(yp + k * 128 + 4);
        float av[8] = {a0.x, a0.y, a0.z, a0.w, a1.x, a1.y, a1.z, a1.w};
        float bv[8] = {b0.x, b0.y, b0.z, b0.w, b1.x, b1.y, b1.z, b1.w};
        #pragma unroll
        for (int i = 0; i < 8; i++)
            #pragma unroll
            for (int j = 0; j < 8; j++)
                acc[i][j] += av[i] * bv[j];
    }
    __syncthreads();   // Xs/Ys reads (incl. norms) complete; reuse as Dt

    // acc -> Dt with norms folded: D = x2 + y2 - 2*dot
    #pragma unroll
    for (int i = 0; i < 8; i++) {
        float xi = x2s[ty * 8 + i];
        #pragma unroll
        for (int j = 0; j < 8; j++)
            Dt[(ty * 8 + i) * 130 + tx * 8 + j] =
                fmaf(-2.0f, acc[i][j], xi + y2s[tx * 8 + j]);
    }
    __syncthreads();

    // 255 tile anti-diagonals, contiguous global runs. Diag smem read stride
    // = 129 floats (odd) -> conflict-free.
    float* outb = g_Ddiag + (size_t)b * LDIAG * NN;
    const int g  = tid >> 7;         // 0..1
    const int lt = tid & 127;
    for (int t = g; t < 255; t += 2) {
        int lo = t - 127; if (lo < 0) lo = 0;
        int hi = t < 127 ? t : 127;
        int il = lo + lt;
        if (il <= hi)
            outb[(size_t)(i0 + j0 + t) * NN + (i0 + il)] = Dt[il * 130 + (t - il)];
    }
}

// ---------------------------------------------------------------------------
// Kernel 2: soft-DTW DP. One CTA per batch, 128 threads, thread t owns rows
// 4t..4t+3 with R state in REGISTERS. Neighbor handoff: shfl_up within warp,
// double-buffered smem for the 3 warp boundaries. One 4-warp barrier/step.
// Softmin: mn - log(1 + exp(mn-mid) + exp(mn-mx))  -> 3 MUFU per cell.
// D prefetched 4 diagonals deep (L2 resident).
// ---------------------------------------------------------------------------
__global__ __launch_bounds__(128) void dp_kernel(float* __restrict__ outp) {
    __shared__ float h1[2][4];       // [parity][warp] : neighbor p1 (diag d-1)
    __shared__ float h2[2][4];       // [parity][warp] : neighbor p2 (diag d-2)

    const int t    = threadIdx.x;
    const int b    = blockIdx.x;
    const int lane = t & 31;
    const int w    = t >> 5;
    const int base = 4 * t;          // first row owned by this thread

    const float4* P = (const float4*)(g_Ddiag + (size_t)b * LDIAG * NN);
    // float4 index for diagonal d: d*128 + t  (rows 4t..4t+3)

    float p1[4], p2[4];
    #pragma unroll
    for (int q = 0; q < 4; q++) { p1[q] = BIGF; p2[q] = BIGF; }
    float nb1 = BIGF, nb2 = BIGF;    // row base-1: value at d-1, d-2

    float4 dbuf[4];
    #pragma unroll
    for (int k = 0; k < 4; k++) dbuf[k] = P[k * 128 + t];

    #pragma unroll 4
    for (int d = 0; d < LDIAG; ++d) {
        float4 Dv = dbuf[d & 3];
        float cur[4];
        bool active = (base <= d) && (d <= base + 3 + (MM - 1));
        if (active) {
            float Darr[4] = {Dv.x, Dv.y, Dv.z, Dv.w};
            #pragma unroll
            for (int q = 0; q < 4; q++) {
                int r = base + q;
                int j = d - r;
                if (j >= 0 && j < MM) {
                    float a, bb;
                    if (q == 0) {
                        if (t == 0) { a = (d == 0) ? 0.0f : BIGF; bb = BIGF; }
                        else        { a = nb2;                    bb = nb1; }
                    } else {
                        a = p2[q - 1]; bb = p1[q - 1];
                    }
                    float c   = p1[q];
                    float lo_ = fminf(a, bb), hi_ = fmaxf(a, bb);
                    float mn  = fminf(lo_, c);
                    float mid = fminf(hi_, fmaxf(lo_, c));
                    float mx  = fmaxf(hi_, c);
                    float sum = 1.0f + __expf(mn - mid) + __expf(mn - mx);
                    cur[q] = Darr[q] + mn - __logf(sum);
                } else {
                    cur[q] = BIGF;
                }
            }
        } else {
            cur[0] = cur[1] = cur[2] = cur[3] = BIGF;
        }

        // Prefetch diagonal d+4 into the slot just consumed
        int nd = d + 4; if (nd > LDIAG - 1) nd = LDIAG - 1;
        dbuf[d & 3] = P[nd * 128 + t];

        // Handoff: next step's neighbor needs (cur[3], pre-rotate p1[3])
        float s1 = cur[3];
        float s2 = p1[3];
        float u1 = __shfl_up_sync(0xffffffffu, s1, 1);
        float u2 = __shfl_up_sync(0xffffffffu, s2, 1);
        int par = (d + 1) & 1;
        if (lane == 31 && w < 3) { h1[par][w] = s1; h2[par][w] = s2; }

        #pragma unroll
        for (int q = 0; q < 4; q++) { p2[q] = p1[q]; p1[q] = cur[q]; }
        if (lane) { nb1 = u1; nb2 = u2; }

        __syncthreads();
        if (lane == 0 && w > 0) { nb1 = h1[par][w - 1]; nb2 = h2[par][w - 1]; }
    }

    if (t == 127) outp[b] = p1[3];   // R[N][M]
}

// ---------------------------------------------------------------------------
extern "C" void kernel_launch(void* const* d_in, const int* in_sizes, int n_in,
                              void* d_out, int out_size) {
    const float* X = (const float*)d_in[0];   // [32, 512, 64]
    const float* Y = (const float*)d_in[1];   // [32, 512, 64]
    float* out = (float*)d_out;               // [32]

    cudaFuncSetAttribute(dist_kernel, cudaFuncAttributeMaxDynamicSharedMemorySize,
                         DIST_SMEM_BYTES);

    dist_kernel<<<dim3(MM / 128, NN / 128, BATCH), 256, DIST_SMEM_BYTES>>>(X, Y);
    dp_kernel<<<BATCH, 128>>>(out);
}

// round 7
// speedup vs baseline: 1.7823x; 1.7823x over previous
#include <cuda_runtime.h>
#include <cuda_bf16.h>
#include <cstdint>

#define BATCH 32
#define NN    512
#define MM    512
#define DD    64
#define LDIAG 1023           // N + M - 1 anti-diagonals
#define BIGF  1e30f

// Scratch: FULL distance (x2 + y2 - 2*dot) in diagonal layout:
//   g_Ddiag[b][d][r] = D[b][r][d-r],  d = r + j (0-based), r = row.
// 32 * 1023 * 512 * 4B = ~64 MB. Invalid slots never read by the DP.
__device__ float g_Ddiag[(size_t)BATCH * LDIAG * NN];

// ---------------------------------------------------------------------------
// Kernel 1: D for a 128x128 tile, 8x8 register microtile per thread,
// k-major (transposed) smem, norms folded, diagonal-layout coalesced store.
// (unchanged from R6 — measured ~45us total with overhead)
// ---------------------------------------------------------------------------
#define DIST_SMEM_BYTES (16896 * 4)

__global__ __launch_bounds__(256) void dist_kernel(const float* __restrict__ X,
                                                   const float* __restrict__ Y) {
    extern __shared__ float sm[];
    float* Xs  = sm;                 // [64][128] k-major
    float* Ys  = sm + 64 * 128;      // [64][128] k-major
    float* Dt  = sm;                 // [128][130] (reuses Xs/Ys after barrier)
    float* x2s = sm + 16640;
    float* y2s = x2s + 128;

    const int b  = blockIdx.z;
    const int i0 = blockIdx.y * 128;
    const int j0 = blockIdx.x * 128;
    const int tid = threadIdx.x;

    const float* Xg = X + ((size_t)b * NN + i0) * DD;
    const float* Yg = Y + ((size_t)b * MM + j0) * DD;

    for (int l = tid; l < 128 * 16; l += 256) {
        int kq = l >> 7;
        int r  = l & 127;
        float4 vx = *(const float4*)(Xg + (size_t)r * DD + kq * 4);
        float4 vy = *(const float4*)(Yg + (size_t)r * DD + kq * 4);
        Xs[(kq * 4 + 0) * 128 + r] = vx.x;
        Xs[(kq * 4 + 1) * 128 + r] = vx.y;
        Xs[(kq * 4 + 2) * 128 + r] = vx.z;
        Xs[(kq * 4 + 3) * 128 + r] = vx.w;
        Ys[(kq * 4 + 0) * 128 + r] = vy.x;
        Ys[(kq * 4 + 1) * 128 + r] = vy.y;
        Ys[(kq * 4 + 2) * 128 + r] = vy.z;
        Ys[(kq * 4 + 3) * 128 + r] = vy.w;
    }
    __syncthreads();

    if (tid < 128) {
        float s = 0.0f;
        #pragma unroll 8
        for (int k = 0; k < 64; ++k) { float v = Xs[k * 128 + tid]; s += v * v; }
        x2s[tid] = s;
    } else {
        int c = tid - 128;
        float s = 0.0f;
        #pragma unroll 8
        for (int k = 0; k < 64; ++k) { float v = Ys[k * 128 + c]; s += v * v; }
        y2s[c] = s;
    }

    const int tx = tid & 15, ty = tid >> 4;
    float acc[8][8];
    #pragma unroll
    for (int i = 0; i < 8; i++)
        #pragma unroll
        for (int j = 0; j < 8; j++) acc[i][j] = 0.0f;

    const float* xp = Xs + ty * 8;
    const float* yp = Ys + tx * 8;
    #pragma unroll 4
    for (int k = 0; k < 64; ++k) {
        float4 a0 = *(const float4*)(xp + k * 128);
        float4 a1 = *(const float4*)(xp + k * 128 + 4);
        float4 b0 = *(const float4*)(yp + k * 128);
        float4 b1 = *(const float4*)(yp + k * 128 + 4);
        float av[8] = {a0.x, a0.y, a0.z, a0.w, a1.x, a1.y, a1.z, a1.w};
        float bv[8] = {b0.x, b0.y, b0.z, b0.w, b1.x, b1.y, b1.z, b1.w};
        #pragma unroll
        for (int i = 0; i < 8; i++)
            #pragma unroll
            for (int j = 0; j < 8; j++)
                acc[i][j] += av[i] * bv[j];
    }
    __syncthreads();

    #pragma unroll
    for (int i = 0; i < 8; i++) {
        float xi = x2s[ty * 8 + i];
        #pragma unroll
        for (int j = 0; j < 8; j++)
            Dt[(ty * 8 + i) * 130 + tx * 8 + j] =
                fmaf(-2.0f, acc[i][j], xi + y2s[tx * 8 + j]);
    }
    __syncthreads();

    float* outb = g_Ddiag + (size_t)b * LDIAG * NN;
    const int g  = tid >> 7;
    const int lt = tid & 127;
    for (int t = g; t < 255; t += 2) {
        int lo = t - 127; if (lo < 0) lo = 0;
        int hi = t < 127 ? t : 127;
        int il = lo + lt;
        if (il <= hi)
            outb[(size_t)(i0 + j0 + t) * NN + (i0 + il)] = Dt[il * 130 + (t - il)];
    }
}

// ---------------------------------------------------------------------------
// Kernel 2: soft-DTW DP. One CTA per batch, 128 threads, thread t owns rows
// 4t..4t+3 in registers. D streamed through a cp.async smem ring (depth 8,
// one commit group per diagonal, wait_group 6 -> 7-step latency slack with
// PRECISE per-group completion, unlike register-ring scoreboard draining).
// Softmin: mn - log(1 + exp(mn-mid) + exp(mn-mx)) -> 3 MUFU per cell.
// ---------------------------------------------------------------------------
__device__ __forceinline__ uint32_t smem_u32(const void* p) {
    uint32_t a;
    asm("{ .reg .u64 t; cvta.to.shared.u64 t, %1; cvt.u32.u64 %0, t; }"
        : "=r"(a) : "l"(p));
    return a;
}

__global__ __launch_bounds__(128) void dp_kernel(float* __restrict__ outp) {
    __shared__ float4 ring[8][128];  // [slot][thread] : rows 4t..4t+3 of a diagonal
    __shared__ float h1[2][4];       // [parity][warp] : neighbor p1 (diag d-1)
    __shared__ float h2[2][4];       // [parity][warp] : neighbor p2 (diag d-2)

    const int t    = threadIdx.x;
    const int b    = blockIdx.x;
    const int lane = t & 31;
    const int w    = t >> 5;
    const int base = 4 * t;          // first row owned by this thread

    const float4* P = (const float4*)(g_Ddiag + (size_t)b * LDIAG * NN);
    const uint32_t ring_t = smem_u32(&ring[0][0]) + (uint32_t)t * 16u;

    // Prologue: prefetch diagonals 0..6 into slots 0..6 (one group each).
    #pragma unroll
    for (int d = 0; d < 7; ++d) {
        const float4* gp = P + d * 128 + t;
        asm volatile("cp.async.cg.shared.global [%0], [%1], 16;\n"
                     :: "r"(ring_t + (uint32_t)d * 2048u), "l"(gp) : "memory");
        asm volatile("cp.async.commit_group;\n" ::: "memory");
    }

    float p1[4], p2[4];
    #pragma unroll
    for (int q = 0; q < 4; q++) { p1[q] = BIGF; p2[q] = BIGF; }
    float nb1 = BIGF, nb2 = BIGF;    // row base-1: value at d-1, d-2

    for (int d = 0; d < LDIAG; ++d) {
        // Oldest group (diag d) must be complete; 6 newer stay in flight.
        asm volatile("cp.async.wait_group 6;\n" ::: "memory");
        float4 Dv = ring[d & 7][t];

        float cur[4];
        bool active = (base <= d) && (d <= base + 3 + (MM - 1));
        if (active) {
            float Darr[4] = {Dv.x, Dv.y, Dv.z, Dv.w};
            #pragma unroll
            for (int q = 0; q < 4; q++) {
                int r = base + q;
                int j = d - r;
                if (j >= 0 && j < MM) {
                    float a, bb;
                    if (q == 0) {
                        if (t == 0) { a = (d == 0) ? 0.0f : BIGF; bb = BIGF; }
                        else        { a = nb2;                    bb = nb1; }
                    } else {
                        a = p2[q - 1]; bb = p1[q - 1];
                    }
                    float c   = p1[q];
                    float lo_ = fminf(a, bb), hi_ = fmaxf(a, bb);
                    float mn  = fminf(lo_, c);
                    float mid = fminf(hi_, fmaxf(lo_, c));
                    float mx  = fmaxf(hi_, c);
                    float sum = 1.0f + __expf(mn - mid) + __expf(mn - mx);
                    cur[q] = Darr[q] + mn - __logf(sum);
                } else {
                    cur[q] = BIGF;
                }
            }
        } else {
            cur[0] = cur[1] = cur[2] = cur[3] = BIGF;
        }

        // Prefetch diagonal d+7 into slot (d+7)&7 (consumed at step d-1 -> free).
        {
            int nd = d + 7; if (nd > LDIAG - 1) nd = LDIAG - 1;
            const float4* gp = P + (size_t)nd * 128 + t;
            asm volatile("cp.async.cg.shared.global [%0], [%1], 16;\n"
                         :: "r"(ring_t + (uint32_t)((d + 7) & 7) * 2048u), "l"(gp)
                         : "memory");
            asm volatile("cp.async.commit_group;\n" ::: "memory");
        }

        // Handoff: next step's lower neighbor needs (cur[3], pre-rotate p1[3]).
        float s1 = cur[3];
        float s2 = p1[3];
        float u1 = __shfl_up_sync(0xffffffffu, s1, 1);
        float u2 = __shfl_up_sync(0xffffffffu, s2, 1);
        int par = (d + 1) & 1;
        if (lane == 31 && w < 3) { h1[par][w] = s1; h2[par][w] = s2; }

        #pragma unroll
        for (int q = 0; q < 4; q++) { p2[q] = p1[q]; p1[q] = cur[q]; }
        if (lane) { nb1 = u1; nb2 = u2; }

        __syncthreads();
        if (lane == 0 && w > 0) { nb1 = h1[par][w - 1]; nb2 = h2[par][w - 1]; }
    }

    if (t == 127) outp[b] = p1[3];   // R[N][M]
}

// ---------------------------------------------------------------------------
extern "C" void kernel_launch(void* const* d_in, const int* in_sizes, int n_in,
                              void* d_out, int out_size) {
    const float* X = (const float*)d_in[0];   // [32, 512, 64]
    const float* Y = (const float*)d_in[1];   // [32, 512, 64]
    float* out = (float*)d_out;               // [32]

    cudaFuncSetAttribute(dist_kernel, cudaFuncAttributeMaxDynamicSharedMemorySize,
                         DIST_SMEM_BYTES);

    dist_kernel<<<dim3(MM / 128, NN / 128, BATCH), 256, DIST_SMEM_BYTES>>>(X, Y);
    dp_kernel<<<BATCH, 128>>>(out);
}

// round 9
// speedup vs baseline: 2.5249x; 1.4167x over previous
#include <cuda_runtime.h>
#include <cuda_bf16.h>
#include <cstdint>

#define BATCH 32
#define NN    512
#define MM    512
#define DD    64
#define LDIAG 1023           // N + M - 1 anti-diagonals
#define BIGF  1e30f

// Scratch: FULL distance (x2 + y2 - 2*dot) in diagonal layout:
//   g_Ddiag[b][d][r] = D[b][r][d-r],  d = r + j (0-based), r = row.
// 32 * 1023 * 512 * 4B = ~64 MB. Invalid slots never read by the DP.
__device__ float g_Ddiag[(size_t)BATCH * LDIAG * NN];

// ---------------------------------------------------------------------------
// Kernel 1: D for a 128x128 tile, 8x8 register microtile per thread,
// k-major (transposed) smem, norms folded, diagonal-layout coalesced store.
// (unchanged — measured ~45-60us incl. overhead, near FMA floor)
// ---------------------------------------------------------------------------
#define DIST_SMEM_BYTES (16896 * 4)

__global__ __launch_bounds__(256) void dist_kernel(const float* __restrict__ X,
                                                   const float* __restrict__ Y) {
    extern __shared__ float sm[];
    float* Xs  = sm;                 // [64][128] k-major
    float* Ys  = sm + 64 * 128;      // [64][128] k-major
    float* Dt  = sm;                 // [128][130] (reuses Xs/Ys after barrier)
    float* x2s = sm + 16640;
    float* y2s = x2s + 128;

    const int b  = blockIdx.z;
    const int i0 = blockIdx.y * 128;
    const int j0 = blockIdx.x * 128;
    const int tid = threadIdx.x;

    const float* Xg = X + ((size_t)b * NN + i0) * DD;
    const float* Yg = Y + ((size_t)b * MM + j0) * DD;

    for (int l = tid; l < 128 * 16; l += 256) {
        int kq = l >> 7;
        int r  = l & 127;
        float4 vx = *(const float4*)(Xg + (size_t)r * DD + kq * 4);
        float4 vy = *(const float4*)(Yg + (size_t)r * DD + kq * 4);
        Xs[(kq * 4 + 0) * 128 + r] = vx.x;
        Xs[(kq * 4 + 1) * 128 + r] = vx.y;
        Xs[(kq * 4 + 2) * 128 + r] = vx.z;
        Xs[(kq * 4 + 3) * 128 + r] = vx.w;
        Ys[(kq * 4 + 0) * 128 + r] = vy.x;
        Ys[(kq * 4 + 1) * 128 + r] = vy.y;
        Ys[(kq * 4 + 2) * 128 + r] = vy.z;
        Ys[(kq * 4 + 3) * 128 + r] = vy.w;
    }
    __syncthreads();

    if (tid < 128) {
        float s = 0.0f;
        #pragma unroll 8
        for (int k = 0; k < 64; ++k) { float v = Xs[k * 128 + tid]; s += v * v; }
        x2s[tid] = s;
    } else {
        int c = tid - 128;
        float s = 0.0f;
        #pragma unroll 8
        for (int k = 0; k < 64; ++k) { float v = Ys[k * 128 + c]; s += v * v; }
        y2s[c] = s;
    }

    const int tx = tid & 15, ty = tid >> 4;
    float acc[8][8];
    #pragma unroll
    for (int i = 0; i < 8; i++)
        #pragma unroll
        for (int j = 0; j < 8; j++) acc[i][j] = 0.0f;

    const float* xp = Xs + ty * 8;
    const float* yp = Ys + tx * 8;
    #pragma unroll 4
    for (int k = 0; k < 64; ++k) {
        float4 a0 = *(const float4*)(xp + k * 128);
        float4 a1 = *(const float4*)(xp + k * 128 + 4);
        float4 b0 = *(const float4*)(yp + k * 128);
        float4 b1 = *(const float4*)(yp + k * 128 + 4);
        float av[8] = {a0.x, a0.y, a0.z, a0.w, a1.x, a1.y, a1.z, a1.w};
        float bv[8] = {b0.x, b0.y, b0.z, b0.w, b1.x, b1.y, b1.z, b1.w};
        #pragma unroll
        for (int i = 0; i < 8; i++)
            #pragma unroll
            for (int j = 0; j < 8; j++)
                acc[i][j] += av[i] * bv[j];
    }
    __syncthreads();

    #pragma unroll
    for (int i = 0; i < 8; i++) {
        float xi = x2s[ty * 8 + i];
        #pragma unroll
        for (int j = 0; j < 8; j++)
            Dt[(ty * 8 + i) * 130 + tx * 8 + j] =
                fmaf(-2.0f, acc[i][j], xi + y2s[tx * 8 + j]);
    }
    __syncthreads();

    float* outb = g_Ddiag + (size_t)b * LDIAG * NN;
    const int g  = tid >> 7;
    const int lt = tid & 127;
    for (int t = g; t < 255; t += 2) {
        int lo = t - 127; if (lo < 0) lo = 0;
        int hi = t < 127 ? t : 127;
        int il = lo + lt;
        if (il <= hi)
            outb[(size_t)(i0 + j0 + t) * NN + (i0 + il)] = Dt[il * 130 + (t - il)];
    }
}

// ---------------------------------------------------------------------------
// Kernel 2: soft-DTW DP. One CTA per batch, 256 threads (8 warps = 2/SMSP for
// latency hiding), thread t owns rows 2t..2t+1 in registers. D streamed
// through a cp.async smem ring (depth 8, one commit group per diagonal,
// wait_group 6 -> precise per-group completion, 7-step latency slack).
// Softmin: mn - log(1 + exp(mn-mid) + exp(mn-mx)) -> 3 MUFU per cell.
// ---------------------------------------------------------------------------
__device__ __forceinline__ uint32_t smem_u32(const void* p) {
    uint32_t a;
    asm("{ .reg .u64 t; cvta.to.shared.u64 t, %1; cvt.u32.u64 %0, t; }"
        : "=r"(a) : "l"(p));
    return a;
}

__global__ __launch_bounds__(256) void dp_kernel(float* __restrict__ outp) {
    __shared__ float2 ring[8][256];  // [slot][thread]: rows 2t,2t+1 of a diagonal
    __shared__ float h1[2][8];       // [parity][warp] : neighbor p1 (diag d-1)
    __shared__ float h2[2][8];       // [parity][warp] : neighbor p2 (diag d-2)

    const int t    = threadIdx.x;
    const int b    = blockIdx.x;
    const int lane = t & 31;
    const int w    = t >> 5;
    const int base = 2 * t;          // first row owned by this thread

    const float2* P = (const float2*)(g_Ddiag + (size_t)b * LDIAG * NN);
    const uint32_t ring_t = smem_u32(&ring[0][0]) + (uint32_t)t * 8u;

    // Prologue: prefetch diagonals 0..6 into slots 0..6 (one group each).
    #pragma unroll
    for (int d = 0; d < 7; ++d) {
        const float2* gp = P + d * 256 + t;
        asm volatile("cp.async.ca.shared.global [%0], [%1], 8;\n"
                     :: "r"(ring_t + (uint32_t)d * 2048u), "l"(gp) : "memory");
        asm volatile("cp.async.commit_group;\n" ::: "memory");
    }

    float p1[2], p2[2];
    #pragma unroll
    for (int q = 0; q < 2; q++) { p1[q] = BIGF; p2[q] = BIGF; }
    float nb1 = BIGF, nb2 = BIGF;    // row base-1: value at d-1, d-2

    for (int d = 0; d < LDIAG; ++d) {
        // Oldest group (diag d) must be complete; 6 newer stay in flight.
        asm volatile("cp.async.wait_group 6;\n" ::: "memory");
        float2 Dv = ring[d & 7][t];

        float cur[2];
        bool active = (base <= d) && (d <= base + 1 + (MM - 1));
        if (active) {
            float Darr[2] = {Dv.x, Dv.y};
            #pragma unroll
            for (int q = 0; q < 2; q++) {
                int r = base + q;
                int j = d - r;
                if (j >= 0 && j < MM) {
                    float a, bb;
                    if (q == 0) {
                        if (t == 0) { a = (d == 0) ? 0.0f : BIGF; bb = BIGF; }
                        else        { a = nb2;                    bb = nb1; }
                    } else {
                        a = p2[0]; bb = p1[0];
                    }
                    float c   = p1[q];
                    float lo_ = fminf(a, bb), hi_ = fmaxf(a, bb);
                    float mn  = fminf(lo_, c);
                    float mid = fminf(hi_, fmaxf(lo_, c));
                    float mx  = fmaxf(hi_, c);
                    float sum = 1.0f + __expf(mn - mid) + __expf(mn - mx);
                    cur[q] = Darr[q] + mn - __logf(sum);
                } else {
                    cur[q] = BIGF;
                }
            }
        } else {
            cur[0] = cur[1] = BIGF;
        }

        // Prefetch diagonal d+7 into slot (d+7)&7 (consumed at step d-1 -> free).
        {
            int nd = d + 7; if (nd > LDIAG - 1) nd = LDIAG - 1;
            const float2* gp = P + (size_t)nd * 256 + t;
            asm volatile("cp.async.ca.shared.global [%0], [%1], 8;\n"
                         :: "r"(ring_t + (uint32_t)((d + 7) & 7) * 2048u), "l"(gp)
                         : "memory");
            asm volatile("cp.async.commit_group;\n" ::: "memory");
        }

        // Handoff: next step's lower neighbor needs (cur[1], pre-rotate p1[1]).
        float s1 = cur[1];
        float s2 = p1[1];
        float u1 = __shfl_up_sync(0xffffffffu, s1, 1);
        float u2 = __shfl_up_sync(0xffffffffu, s2, 1);
        int par = (d + 1) & 1;
        if (lane == 31 && w < 7) { h1[par][w] = s1; h2[par][w] = s2; }

        #pragma unroll
        for (int q = 0; q < 2; q++) { p2[q] = p1[q]; p1[q] = cur[q]; }
        if (lane) { nb1 = u1; nb2 = u2; }

        __syncthreads();
        if (lane == 0 && w > 0) { nb1 = h1[par][w - 1]; nb2 = h2[par][w - 1]; }
    }

    if (t == 255) outp[b] = p1[1];   // R[N][M]
}

// ---------------------------------------------------------------------------
extern "C" void kernel_launch(void* const* d_in, const int* in_sizes, int n_in,
                              void* d_out, int out_size) {
    const float* X = (const float*)d_in[0];   // [32, 512, 64]
    const float* Y = (const float*)d_in[1];   // [32, 512, 64]
    float* out = (float*)d_out;               // [32]

    cudaFuncSetAttribute(dist_kernel, cudaFuncAttributeMaxDynamicSharedMemorySize,
                         DIST_SMEM_BYTES);

    dist_kernel<<<dim3(MM / 128, NN / 128, BATCH), 256, DIST_SMEM_BYTES>>>(X, Y);
    dp_kernel<<<BATCH, 256>>>(out);
}

// round 11
// speedup vs baseline: 3.0651x; 1.2139x over previous
#include <cuda_runtime.h>
#include <cuda_bf16.h>
#include <cstdint>

#define BATCH 32
#define NN    512
#define MM    512
#define DD    64
#define LDIAG 1023           // N + M - 1 anti-diagonals
#define BIGF  1e30f

// Scratch: FULL distance (x2 + y2 - 2*dot) in diagonal layout:
//   g_Ddiag[b][d][r] = D[b][r][d-r],  d = r + j (0-based), r = row.
// 32 * 1023 * 512 * 4B = ~64 MB. Invalid slots never read by the DP.
__device__ float g_Ddiag[(size_t)BATCH * LDIAG * NN];

// ---------------------------------------------------------------------------
// Kernel 1: D for a 128x128 tile, 8x8 register microtile per thread,
// k-major (transposed) smem, norms folded, diagonal-layout coalesced store.
// (unchanged — near FMA floor, ~45-60us incl. overhead)
// ---------------------------------------------------------------------------
#define DIST_SMEM_BYTES (16896 * 4)

__global__ __launch_bounds__(256) void dist_kernel(const float* __restrict__ X,
                                                   const float* __restrict__ Y) {
    extern __shared__ float sm[];
    float* Xs  = sm;                 // [64][128] k-major
    float* Ys  = sm + 64 * 128;      // [64][128] k-major
    float* Dt  = sm;                 // [128][130] (reuses Xs/Ys after barrier)
    float* x2s = sm + 16640;
    float* y2s = x2s + 128;

    const int b  = blockIdx.z;
    const int i0 = blockIdx.y * 128;
    const int j0 = blockIdx.x * 128;
    const int tid = threadIdx.x;

    const float* Xg = X + ((size_t)b * NN + i0) * DD;
    const float* Yg = Y + ((size_t)b * MM + j0) * DD;

    for (int l = tid; l < 128 * 16; l += 256) {
        int kq = l >> 7;
        int r  = l & 127;
        float4 vx = *(const float4*)(Xg + (size_t)r * DD + kq * 4);
        float4 vy = *(const float4*)(Yg + (size_t)r * DD + kq * 4);
        Xs[(kq * 4 + 0) * 128 + r] = vx.x;
        Xs[(kq * 4 + 1) * 128 + r] = vx.y;
        Xs[(kq * 4 + 2) * 128 + r] = vx.z;
        Xs[(kq * 4 + 3) * 128 + r] = vx.w;
        Ys[(kq * 4 + 0) * 128 + r] = vy.x;
        Ys[(kq * 4 + 1) * 128 + r] = vy.y;
        Ys[(kq * 4 + 2) * 128 + r] = vy.z;
        Ys[(kq * 4 + 3) * 128 + r] = vy.w;
    }
    __syncthreads();

    if (tid < 128) {
        float s = 0.0f;
        #pragma unroll 8
        for (int k = 0; k < 64; ++k) { float v = Xs[k * 128 + tid]; s += v * v; }
        x2s[tid] = s;
    } else {
        int c = tid - 128;
        float s = 0.0f;
        #pragma unroll 8
        for (int k = 0; k < 64; ++k) { float v = Ys[k * 128 + c]; s += v * v; }
        y2s[c] = s;
    }

    const int tx = tid & 15, ty = tid >> 4;
    float acc[8][8];
    #pragma unroll
    for (int i = 0; i < 8; i++)
        #pragma unroll
        for (int j = 0; j < 8; j++) acc[i][j] = 0.0f;

    const float* xp = Xs + ty * 8;
    const float* yp = Ys + tx * 8;
    #pragma unroll 4
    for (int k = 0; k < 64; ++k) {
        float4 a0 = *(const float4*)(xp + k * 128);
        float4 a1 = *(const float4*)(xp + k * 128 + 4);
        float4 b0 = *(const float4*)(yp + k * 128);
        float4 b1 = *(const float4*)(yp + k * 128 + 4);
        float av[8] = {a0.x, a0.y, a0.z, a0.w, a1.x, a1.y, a1.z, a1.w};
        float bv[8] = {b0.x, b0.y, b0.z, b0.w, b1.x, b1.y, b1.z, b1.w};
        #pragma unroll
        for (int i = 0; i < 8; i++)
            #pragma unroll
            for (int j = 0; j < 8; j++)
                acc[i][j] += av[i] * bv[j];
    }
    __syncthreads();

    #pragma unroll
    for (int i = 0; i < 8; i++) {
        float xi = x2s[ty * 8 + i];
        #pragma unroll
        for (int j = 0; j < 8; j++)
            Dt[(ty * 8 + i) * 130 + tx * 8 + j] =
                fmaf(-2.0f, acc[i][j], xi + y2s[tx * 8 + j]);
    }
    __syncthreads();

    float* outb = g_Ddiag + (size_t)b * LDIAG * NN;
    const int g  = tid >> 7;
    const int lt = tid & 127;
    for (int t = g; t < 255; t += 2) {
        int lo = t - 127; if (lo < 0) lo = 0;
        int hi = t < 127 ? t : 127;
        int il = lo + lt;
        if (il <= hi)
            outb[(size_t)(i0 + j0 + t) * NN + (i0 + il)] = Dt[il * 130 + (t - il)];
    }
}

// ---------------------------------------------------------------------------
// Kernel 2: soft-DTW DP. One CTA per batch, 512 threads (16 warps = 4/SMSP
// for latency hiding), thread t owns row t with state in REGISTERS.
// D streamed via cp.async smem ring (depth 8, one group per diagonal,
// wait_group 6 -> precise per-group completion). Handoff: shfl_up within
// warp + parity double-buffered smem at warp seams. One barrier per step.
// Softmin: mn - log(1 + exp(mn-mid) + exp(mn-mx)) -> 3 MUFU per cell.
// ---------------------------------------------------------------------------
__device__ __forceinline__ uint32_t smem_u32(const void* p) {
    uint32_t a;
    asm("{ .reg .u64 t; cvta.to.shared.u64 t, %1; cvt.u32.u64 %0, t; }"
        : "=r"(a) : "l"(p));
    return a;
}

__global__ __launch_bounds__(512) void dp_kernel(float* __restrict__ outp) {
    __shared__ float ring[8][512];   // [slot][thread]: row t of a diagonal
    __shared__ float h1[2][16];      // [parity][warp] : seam neighbor p1 (d-1)
    __shared__ float h2[2][16];      // [parity][warp] : seam neighbor p2 (d-2)

    const int t    = threadIdx.x;
    const int b    = blockIdx.x;
    const int lane = t & 31;
    const int w    = t >> 5;

    const float* P = g_Ddiag + (size_t)b * LDIAG * NN;
    const uint32_t ring_t = smem_u32(&ring[0][0]) + (uint32_t)t * 4u;

    // Prologue: prefetch diagonals 0..6 into slots 0..6 (one group each).
    #pragma unroll
    for (int d = 0; d < 7; ++d) {
        const float* gp = P + d * 512 + t;
        asm volatile("cp.async.ca.shared.global [%0], [%1], 4;\n"
                     :: "r"(ring_t + (uint32_t)d * 2048u), "l"(gp) : "memory");
        asm volatile("cp.async.commit_group;\n" ::: "memory");
    }

    float p1 = BIGF, p2 = BIGF;      // this row's values at diag d-1, d-2
    float nb1 = BIGF, nb2 = BIGF;    // row t-1's values at diag d-1, d-2

    for (int d = 0; d < LDIAG; ++d) {
        // Oldest group (diag d) must be complete; 6 newer stay in flight.
        asm volatile("cp.async.wait_group 6;\n" ::: "memory");
        float Dv = ring[d & 7][t];

        float cur = BIGF;
        if ((unsigned)(d - t) < (unsigned)MM) {   // j = d - t in [0, M)
            float a, bb;
            if (t == 0) { a = (d == 0) ? 0.0f : BIGF; bb = BIGF; }
            else        { a = nb2;                    bb = nb1; }
            float c   = p1;
            float lo_ = fminf(a, bb), hi_ = fmaxf(a, bb);
            float mn  = fminf(lo_, c);
            float mid = fminf(hi_, fmaxf(lo_, c));
            float mx  = fmaxf(hi_, c);
            float sum = 1.0f + __expf(mn - mid) + __expf(mn - mx);
            cur = Dv + mn - __logf(sum);
        }

        // Prefetch diagonal d+7 into slot (d+7)&7 (consumed at step d-1 -> free).
        {
            int nd = d + 7; if (nd > LDIAG - 1) nd = LDIAG - 1;
            const float* gp = P + (size_t)nd * 512 + t;
            asm volatile("cp.async.ca.shared.global [%0], [%1], 4;\n"
                         :: "r"(ring_t + (uint32_t)((d + 7) & 7) * 2048u), "l"(gp)
                         : "memory");
            asm volatile("cp.async.commit_group;\n" ::: "memory");
        }

        // Handoff: next step's lower neighbor needs (cur, pre-rotate p1).
        float s1 = cur;
        float s2 = p1;
        float u1 = __shfl_up_sync(0xffffffffu, s1, 1);
        float u2 = __shfl_up_sync(0xffffffffu, s2, 1);
        int par = (d + 1) & 1;
        if (lane == 31 && w < 15) { h1[par][w] = s1; h2[par][w] = s2; }

        p2 = p1; p1 = cur;
        if (lane) { nb1 = u1; nb2 = u2; }

        __syncthreads();
        if (lane == 0 && w > 0) { nb1 = h1[par][w - 1]; nb2 = h2[par][w - 1]; }
    }

    if (t == NN - 1) outp[b] = p1;   // R[N][M]
}

// ---------------------------------------------------------------------------
extern "C" void kernel_launch(void* const* d_in, const int* in_sizes, int n_in,
                              void* d_out, int out_size) {
    const float* X = (const float*)d_in[0];   // [32, 512, 64]
    const float* Y = (const float*)d_in[1];   // [32, 512, 64]
    float* out = (float*)d_out;               // [32]

    cudaFuncSetAttribute(dist_kernel, cudaFuncAttributeMaxDynamicSharedMemorySize,
                         DIST_SMEM_BYTES);

    dist_kernel<<<dim3(MM / 128, NN / 128, BATCH), 256, DIST_SMEM_BYTES>>>(X, Y);
    dp_kernel<<<BATCH, 512>>>(out);
}